// round 6
// baseline (speedup 1.0000x reference)
#include <cuda_runtime.h>
#include <math.h>

// rbfLayer, round 6: single-gather record layout.
// Pre-pass packs pos+features into 64B records; main kernel fetches the whole
// per-edge working set (pos + 8 feats) with ONE LDG.128 per lane-quad
// (1 cache-line touch per edge instead of 2). No smem staging, no barrier.
// Lane slice map: t0->slice0 (pos,f0,f1), t1->slice1 (f2..f5, uses f2,f3),
//                 t2->slice2 (f6,f7),     t3->slice1 (uses f4,f5).
// j-pair per lane: jmap = {0,2,6,4}.

#define PTS_PER_BLOCK 32
#define BLOCK_THREADS 128
#define MAX_N 262144

typedef unsigned long long u64;

__device__ __align__(128) float4 g_rec[MAX_N * 4];   // 64B record per point

__device__ __forceinline__ u64 pack2(float lo, float hi) {
    u64 r;
    asm("mov.b64 %0, {%1,%2};" : "=l"(r)
        : "r"(__float_as_int(lo)), "r"(__float_as_int(hi)));
    return r;
}
__device__ __forceinline__ void unpack2(u64 v, float& lo, float& hi) {
    int a, b;
    asm("mov.b64 {%0,%1}, %2;" : "=r"(a), "=r"(b) : "l"(v));
    lo = __int_as_float(a); hi = __int_as_float(b);
}
__device__ __forceinline__ u64 fma2(u64 a, u64 b, u64 c) {
    u64 d;
    asm("fma.rn.f32x2 %0, %1, %2, %3;" : "=l"(d) : "l"(a), "l"(b), "l"(c));
    return d;
}
__device__ __forceinline__ u64 mul2(u64 a, u64 b) {
    u64 d;
    asm("mul.rn.f32x2 %0, %1, %2;" : "=l"(d) : "l"(a), "l"(b));
    return d;
}

// ---------------- Pre-pass: build records ----------------
__global__ __launch_bounds__(256)
void pack_kernel(const float2* __restrict__ pos,
                 const float4* __restrict__ feat4,   // [N][2] float4
                 int n_pts)
{
    int i = blockIdx.x * 256 + threadIdx.x;
    if (i >= n_pts) return;
    float2 p = __ldg(&pos[i]);
    float4 a = __ldg(&feat4[i * 2 + 0]);
    float4 b = __ldg(&feat4[i * 2 + 1]);
    g_rec[i * 4 + 0] = make_float4(p.x, p.y, a.x, a.y);
    g_rec[i * 4 + 1] = make_float4(a.z, a.w, b.x, b.y);
    g_rec[i * 4 + 2] = make_float4(b.z, b.w, 0.0f, 0.0f);
}

// ---------------- geometry + decode ----------------
__device__ __forceinline__ void edge_geom(float dx, float dy,
                                          float& sr, float& sa) {
    float d2 = fmaxf(fmaf(dx, dx, dy * dy), 1e-24f);
    float rinv = rsqrtf(d2);
    sr = d2 * rinv * 1.5f;

    float ax = fabsf(dx), ay = fabsf(dy);
    float mn = fminf(ax, ay);
    float mx = fmaxf(fmaxf(ax, ay), 1e-30f);
    float tq = __fdividef(mn, mx);
    float t2 = tq * tq;
    float pl = -0.0117212f;
    pl = fmaf(pl, t2, 0.05265332f);
    pl = fmaf(pl, t2, -0.11643287f);
    pl = fmaf(pl, t2, 0.19354346f);
    pl = fmaf(pl, t2, -0.33262347f);
    pl = fmaf(pl, t2, 0.99997726f);
    float ang = pl * tq;
    if (ay > ax) ang = 1.5707963267948966f - ang;
    if (dx < 0.0f) ang = 3.141592653589793f - ang;
    float th = ang * 0.3183098861837907f;
    th = (dy < 0.0f) ? -th : th;
    sa = fmaf(th, 2.0f, 2.0f);
}

__device__ __forceinline__ void decode_w(float sr, float sa,
                                         float4& WA, float4& WR) {
    int   kr = (int)sr;
    float fr = sr - (float)kr;
    int   ka = (int)sa;
    float fa = sa - (float)ka;
    int   k0 = ka & 3;
    int   k1 = (ka + 1) & 3;

    WA.x = (k0 == 0) ? (1.0f - fa) : ((k1 == 0) ? fa : 0.0f);
    WA.y = (k0 == 1) ? (1.0f - fa) : ((k1 == 1) ? fa : 0.0f);
    WA.z = (k0 == 2) ? (1.0f - fa) : ((k1 == 2) ? fa : 0.0f);
    WA.w = (k0 == 3) ? (1.0f - fa) : ((k1 == 3) ? fa : 0.0f);

    WR.x = (kr == 0) ? (1.0f - fr) : 0.0f;
    WR.y = (kr == 1) ? (1.0f - fr) : ((kr == 0) ? fr : 0.0f);
    WR.z = (kr == 2) ? (1.0f - fr) : ((kr == 1) ? fr : 0.0f);
    WR.w = (kr == 2) ? fr : 0.0f;
}

__device__ __forceinline__ void accum16(const float4& WA, const float4& WR,
                                        u64 fv2, u64 Zp[16]) {
    u64 t0 = mul2(pack2(WA.x, WA.x), fv2);
    u64 t1 = mul2(pack2(WA.y, WA.y), fv2);
    u64 t2 = mul2(pack2(WA.z, WA.z), fv2);
    u64 t3 = mul2(pack2(WA.w, WA.w), fv2);
    u64 r0 = pack2(WR.x, WR.x);
    u64 r1 = pack2(WR.y, WR.y);
    u64 r2 = pack2(WR.z, WR.z);
    u64 r3 = pack2(WR.w, WR.w);

    Zp[0]  = fma2(r0, t0, Zp[0]);   Zp[1]  = fma2(r0, t1, Zp[1]);
    Zp[2]  = fma2(r0, t2, Zp[2]);   Zp[3]  = fma2(r0, t3, Zp[3]);
    Zp[4]  = fma2(r1, t0, Zp[4]);   Zp[5]  = fma2(r1, t1, Zp[5]);
    Zp[6]  = fma2(r1, t2, Zp[6]);   Zp[7]  = fma2(r1, t3, Zp[7]);
    Zp[8]  = fma2(r2, t0, Zp[8]);   Zp[9]  = fma2(r2, t1, Zp[9]);
    Zp[10] = fma2(r2, t2, Zp[10]);  Zp[11] = fma2(r2, t3, Zp[11]);
    Zp[12] = fma2(r3, t0, Zp[12]);  Zp[13] = fma2(r3, t1, Zp[13]);
    Zp[14] = fma2(r3, t2, Zp[14]);  Zp[15] = fma2(r3, t3, Zp[15]);
}

__device__ __forceinline__ int quad_comp(const int4& q, int c) {
    return (c == 0) ? q.x : (c == 1) ? q.y : (c == 2) ? q.z : q.w;
}

__global__ __launch_bounds__(BLOCK_THREADS, 6)
void rbf_layer_kernel(const float2* __restrict__ pos,
                      const float*  __restrict__ feat,
                      const float*  __restrict__ kern,
                      const int*    __restrict__ nbrs,
                      const int*    __restrict__ rsp,
                      float*        __restrict__ out,
                      int n_pts, int use_rec)
{
    __shared__ float4 skp4[8 * 8 * 4];    // K repacked per lane-role
    int tid = threadIdx.x;

    for (int idx = tid; idx < 256; idx += BLOCK_THREADS) {
        int tt  = idx & 3;
        int nm2 = (idx >> 2) & 7;
        int i   = idx >> 5;
        int jm  = (tt == 0) ? 0 : (tt == 1) ? 2 : (tt == 2) ? 6 : 4;
        int n0 = 2 * nm2, n1 = 2 * nm2 + 1;
        skp4[idx] = make_float4(kern[(i * 8 + jm)     * 16 + n0],
                                kern[(i * 8 + jm + 1) * 16 + n0],
                                kern[(i * 8 + jm)     * 16 + n1],
                                kern[(i * 8 + jm + 1) * 16 + n1]);
    }
    __syncthreads();

    int gid   = blockIdx.x * BLOCK_THREADS + tid;
    int point = gid >> 2;
    int t     = tid & 3;
    int base  = (tid & 31) & ~3;          // group base lane within warp

    bool valid = (point < n_pts);
    int pclamp = valid ? point : 0;

    int beg = valid ? __ldg(rsp + pclamp)     : 0;
    int end = valid ? __ldg(rsp + pclamp + 1) : 0;
    int cnt = end - beg;

    bool staged = valid && (cnt == 16) && ((beg & 3) == 0) && use_rec;
    bool all_staged = __all_sync(0xffffffffu, staged);

    u64 Zp[16];
    #pragma unroll
    for (int k = 0; k < 16; ++k) Zp[k] = 0ull;

    const int sl = (t == 3) ? 1 : t;      // record slice this lane reads

    if (all_staged) {
        float2 pp = __ldg(&pos[point]);
        // lane t holds edge ids 4t..4t+3 of its point
        int4 nbq = *(const int4*)(nbrs + beg + 4 * t);

        // prologue: fetch step-0 record
        int nb0 = __shfl_sync(0xffffffffu, nbq.x, base);
        float4 R = __ldg(&g_rec[(unsigned)nb0 * 4 + sl]);

        #pragma unroll
        for (int s = 0; s < 16; ++s) {
            float4 Rn;
            if (s < 15) {   // prefetch next record (pipeline depth 1)
                int c   = (s + 1) & 3;
                int src = base + ((s + 1) >> 2);
                int nbn = __shfl_sync(0xffffffffu, quad_comp(nbq, c), src);
                Rn = __ldg(&g_rec[(unsigned)nbn * 4 + sl]);
            }
            // geometry from lane0's slice (pos lives in R.x,R.y there)
            float sr0, sa0;
            edge_geom(R.x - pp.x, R.y - pp.y, sr0, sa0);
            float sr = __shfl_sync(0xffffffffu, sr0, base);
            float sa = __shfl_sync(0xffffffffu, sa0, base);
            float4 WA, WR;
            decode_w(sr, sa, WA, WR);
            // feature pair for this lane: t0,t3 -> (z,w); t1,t2 -> (x,y)
            u64 fv2 = (t == 0 || t == 3) ? pack2(R.z, R.w) : pack2(R.x, R.y);
            accum16(WA, WR, fv2, Zp);
            R = Rn;
        }
    } else if (valid) {
        const float2* f2 = (const float2*)feat;
        const float2 pp = __ldg(&pos[pclamp]);
        int jslot = (t < 2) ? t : (5 - t);   // {0,1,3,2}: float2 index of j-pair
        for (int e = beg; e < end; ++e) {
            int nb = __ldg(nbrs + e);
            float2 q = __ldg(&pos[nb]);
            float sr, sa;
            edge_geom(q.x - pp.x, q.y - pp.y, sr, sa);
            float4 WA, WR;
            decode_w(sr, sa, WA, WR);
            float2 fv = __ldg(&f2[nb * 4 + jslot]);
            accum16(WA, WR, pack2(fv.x, fv.y), Zp);
        }
    }

    // ---- Epilogue: pr[i] = sum_nm <K[i][jpair(t)][nm], Zp[nm]>, hadd ----
    float pr[8];
    #pragma unroll
    for (int i = 0; i < 8; ++i) {
        u64 acc = 0ull;
        #pragma unroll
        for (int nm2 = 0; nm2 < 8; ++nm2) {
            float4 kk = skp4[(i * 8 + nm2) * 4 + t];
            acc = fma2(pack2(kk.x, kk.y), Zp[2 * nm2],     acc);
            acc = fma2(pack2(kk.z, kk.w), Zp[2 * nm2 + 1], acc);
        }
        float lo, hi;
        unpack2(acc, lo, hi);
        pr[i] = lo + hi;
    }

    #pragma unroll
    for (int i = 0; i < 8; ++i) {
        pr[i] += __shfl_xor_sync(0xffffffffu, pr[i], 1);
        pr[i] += __shfl_xor_sync(0xffffffffu, pr[i], 2);
    }

    if (valid) {
        float o0 = pr[0], o1 = pr[4];
        if (t == 1) { o0 = pr[1]; o1 = pr[5]; }
        if (t == 2) { o0 = pr[2]; o1 = pr[6]; }
        if (t == 3) { o0 = pr[3]; o1 = pr[7]; }
        out[point * 8 + t]     = o0;
        out[point * 8 + 4 + t] = o1;
    }
}

extern "C" void kernel_launch(void* const* d_in, const int* in_sizes, int n_in,
                              void* d_out, int out_size)
{
    const float* positions  = (const float*)d_in[0];
    const float* features   = (const float*)d_in[1];
    const float* kernel     = (const float*)d_in[2];
    const int*   neighbors  = (const int*)d_in[3];
    const int*   row_splits = (const int*)d_in[4];
    float*       out        = (float*)d_out;

    int n_pts = in_sizes[0] / 2;
    int use_rec = (n_pts <= MAX_N) ? 1 : 0;

    if (use_rec) {
        pack_kernel<<<(n_pts + 255) / 256, 256>>>(
            (const float2*)positions, (const float4*)features, n_pts);
    }

    int blocks = (n_pts + PTS_PER_BLOCK - 1) / PTS_PER_BLOCK;
    rbf_layer_kernel<<<blocks, BLOCK_THREADS>>>(
        (const float2*)positions, features, kernel, neighbors, row_splits,
        out, n_pts, use_rec);
}

// round 7
// speedup vs baseline: 1.0548x; 1.0548x over previous
#include <cuda_runtime.h>
#include <math.h>

// rbfLayer, round 7: self-sufficient record slices, zero mainloop shuffles.
// Record per point = 64B, slice t (16B) = (px, py, f[2t], f[2t+1]).
// 4 lanes per point; lane t loads its own slice of each neighbor record
// (the 4 lanes of a group hit ONE cache line per edge), computes geometry
// locally (SIMT-free), accumulates Z[16 nm] x j-pair in f32x2.
// Epilogue kernel K held in shared as u64 pairs -> LDS.128 feeds fma2 directly.

#define PTS_PER_BLOCK 32
#define BLOCK_THREADS 128
#define MAX_N 262144

typedef unsigned long long u64;

__device__ __align__(128) float4 g_rec[MAX_N * 4];   // 64B record per point

__device__ __forceinline__ u64 pack2(float lo, float hi) {
    u64 r;
    asm("mov.b64 %0, {%1,%2};" : "=l"(r)
        : "r"(__float_as_int(lo)), "r"(__float_as_int(hi)));
    return r;
}
__device__ __forceinline__ void unpack2(u64 v, float& lo, float& hi) {
    int a, b;
    asm("mov.b64 {%0,%1}, %2;" : "=r"(a), "=r"(b) : "l"(v));
    lo = __int_as_float(a); hi = __int_as_float(b);
}
__device__ __forceinline__ u64 fma2(u64 a, u64 b, u64 c) {
    u64 d;
    asm("fma.rn.f32x2 %0, %1, %2, %3;" : "=l"(d) : "l"(a), "l"(b), "l"(c));
    return d;
}
__device__ __forceinline__ u64 mul2(u64 a, u64 b) {
    u64 d;
    asm("mul.rn.f32x2 %0, %1, %2;" : "=l"(d) : "l"(a), "l"(b));
    return d;
}

// ---------------- Pre-pass: build records ----------------
__global__ __launch_bounds__(256)
void pack_kernel(const float2* __restrict__ pos,
                 const float2* __restrict__ feat2,   // [N][4] float2
                 int n_pts)
{
    int i = blockIdx.x * 256 + threadIdx.x;
    if (i >= n_pts) return;
    float2 p = __ldg(&pos[i]);
    float2 f0 = __ldg(&feat2[i * 4 + 0]);
    float2 f1 = __ldg(&feat2[i * 4 + 1]);
    float2 f2 = __ldg(&feat2[i * 4 + 2]);
    float2 f3 = __ldg(&feat2[i * 4 + 3]);
    g_rec[i * 4 + 0] = make_float4(p.x, p.y, f0.x, f0.y);
    g_rec[i * 4 + 1] = make_float4(p.x, p.y, f1.x, f1.y);
    g_rec[i * 4 + 2] = make_float4(p.x, p.y, f2.x, f2.y);
    g_rec[i * 4 + 3] = make_float4(p.x, p.y, f3.x, f3.y);
}

// ---------------- geometry + decode ----------------
__device__ __forceinline__ void edge_geom(float dx, float dy,
                                          float& sr, float& sa) {
    float d2 = fmaxf(fmaf(dx, dx, dy * dy), 1e-24f);
    float rinv = rsqrtf(d2);
    sr = d2 * rinv * 1.5f;

    float ax = fabsf(dx), ay = fabsf(dy);
    float mn = fminf(ax, ay);
    float mx = fmaxf(fmaxf(ax, ay), 1e-30f);
    float tq = __fdividef(mn, mx);
    float t2 = tq * tq;
    float pl = -0.0117212f;
    pl = fmaf(pl, t2, 0.05265332f);
    pl = fmaf(pl, t2, -0.11643287f);
    pl = fmaf(pl, t2, 0.19354346f);
    pl = fmaf(pl, t2, -0.33262347f);
    pl = fmaf(pl, t2, 0.99997726f);
    float ang = pl * tq;
    if (ay > ax) ang = 1.5707963267948966f - ang;
    if (dx < 0.0f) ang = 3.141592653589793f - ang;
    float th = ang * 0.3183098861837907f;
    th = (dy < 0.0f) ? -th : th;
    sa = fmaf(th, 2.0f, 2.0f);
}

__device__ __forceinline__ void decode_w(float sr, float sa,
                                         float4& WA, float4& WR) {
    int   kr = (int)sr;
    float fr = sr - (float)kr;
    int   ka = (int)sa;
    float fa = sa - (float)ka;
    int   k0 = ka & 3;
    int   k1 = (ka + 1) & 3;

    WA.x = (k0 == 0) ? (1.0f - fa) : ((k1 == 0) ? fa : 0.0f);
    WA.y = (k0 == 1) ? (1.0f - fa) : ((k1 == 1) ? fa : 0.0f);
    WA.z = (k0 == 2) ? (1.0f - fa) : ((k1 == 2) ? fa : 0.0f);
    WA.w = (k0 == 3) ? (1.0f - fa) : ((k1 == 3) ? fa : 0.0f);

    WR.x = (kr == 0) ? (1.0f - fr) : 0.0f;
    WR.y = (kr == 1) ? (1.0f - fr) : ((kr == 0) ? fr : 0.0f);
    WR.z = (kr == 2) ? (1.0f - fr) : ((kr == 1) ? fr : 0.0f);
    WR.w = (kr == 2) ? fr : 0.0f;
}

__device__ __forceinline__ void accum16(const float4& WA, const float4& WR,
                                        u64 fv2, u64 Zp[16]) {
    u64 t0 = mul2(pack2(WA.x, WA.x), fv2);
    u64 t1 = mul2(pack2(WA.y, WA.y), fv2);
    u64 t2 = mul2(pack2(WA.z, WA.z), fv2);
    u64 t3 = mul2(pack2(WA.w, WA.w), fv2);
    u64 r0 = pack2(WR.x, WR.x);
    u64 r1 = pack2(WR.y, WR.y);
    u64 r2 = pack2(WR.z, WR.z);
    u64 r3 = pack2(WR.w, WR.w);

    Zp[0]  = fma2(r0, t0, Zp[0]);   Zp[1]  = fma2(r0, t1, Zp[1]);
    Zp[2]  = fma2(r0, t2, Zp[2]);   Zp[3]  = fma2(r0, t3, Zp[3]);
    Zp[4]  = fma2(r1, t0, Zp[4]);   Zp[5]  = fma2(r1, t1, Zp[5]);
    Zp[6]  = fma2(r1, t2, Zp[6]);   Zp[7]  = fma2(r1, t3, Zp[7]);
    Zp[8]  = fma2(r2, t0, Zp[8]);   Zp[9]  = fma2(r2, t1, Zp[9]);
    Zp[10] = fma2(r2, t2, Zp[10]);  Zp[11] = fma2(r2, t3, Zp[11]);
    Zp[12] = fma2(r3, t0, Zp[12]);  Zp[13] = fma2(r3, t1, Zp[13]);
    Zp[14] = fma2(r3, t2, Zp[14]);  Zp[15] = fma2(r3, t3, Zp[15]);
}

__global__ __launch_bounds__(BLOCK_THREADS, 6)
void rbf_layer_kernel(const float2* __restrict__ pos,
                      const float*  __restrict__ feat,
                      const float*  __restrict__ kern,
                      const int*    __restrict__ nbrs,
                      const int*    __restrict__ rsp,
                      float*        __restrict__ out,
                      int n_pts, int use_rec)
{
    // sk2[(i*8+nm2)*4 + t] = { pack(K[i][2t][2nm2],   K[i][2t+1][2nm2]),
    //                          pack(K[i][2t][2nm2+1], K[i][2t+1][2nm2+1]) }
    __shared__ ulonglong2 sk2[8 * 8 * 4];   // 4 KB
    int tid = threadIdx.x;

    for (int idx = tid; idx < 256; idx += BLOCK_THREADS) {
        int tt  = idx & 3;
        int nm2 = (idx >> 2) & 7;
        int i   = idx >> 5;
        int n0 = 2 * nm2, n1 = 2 * nm2 + 1;
        ulonglong2 v;
        v.x = pack2(kern[(i * 8 + 2 * tt)     * 16 + n0],
                    kern[(i * 8 + 2 * tt + 1) * 16 + n0]);
        v.y = pack2(kern[(i * 8 + 2 * tt)     * 16 + n1],
                    kern[(i * 8 + 2 * tt + 1) * 16 + n1]);
        sk2[idx] = v;
    }
    __syncthreads();

    int gid   = blockIdx.x * BLOCK_THREADS + tid;
    int point = gid >> 2;
    int t     = tid & 3;

    bool valid = (point < n_pts);
    int pclamp = valid ? point : 0;

    int beg = valid ? __ldg(rsp + pclamp)     : 0;
    int end = valid ? __ldg(rsp + pclamp + 1) : 0;
    int cnt = end - beg;

    bool staged = valid && (cnt == 16) && ((beg & 3) == 0) && use_rec;

    u64 Zp[16];
    #pragma unroll
    for (int k = 0; k < 16; ++k) Zp[k] = 0ull;

    if (staged) {
        float2 pp = __ldg(&pos[point]);
        // all 16 neighbor ids (broadcast within the group -> cheap)
        const int4* nb4 = (const int4*)(nbrs + beg);
        int4 q0 = __ldg(nb4 + 0);
        int4 q1 = __ldg(nb4 + 1);
        int4 q2 = __ldg(nb4 + 2);
        int4 q3 = __ldg(nb4 + 3);
        int nb[16] = {q0.x, q0.y, q0.z, q0.w, q1.x, q1.y, q1.z, q1.w,
                      q2.x, q2.y, q2.z, q2.w, q3.x, q3.y, q3.z, q3.w};

        // prologue fetch
        float4 R = __ldg(&g_rec[(unsigned)nb[0] * 4 + t]);

        #pragma unroll
        for (int s = 0; s < 16; ++s) {
            float4 Rn;
            if (s < 15)
                Rn = __ldg(&g_rec[(unsigned)nb[s + 1] * 4 + t]);
            float sr, sa;
            edge_geom(R.x - pp.x, R.y - pp.y, sr, sa);
            float4 WA, WR;
            decode_w(sr, sa, WA, WR);
            accum16(WA, WR, pack2(R.z, R.w), Zp);
            R = Rn;
        }
    } else if (valid) {
        const float2* f2 = (const float2*)feat;
        const float2 pp = __ldg(&pos[pclamp]);
        for (int e = beg; e < end; ++e) {
            int nb = __ldg(nbrs + e);
            float2 q = __ldg(&pos[nb]);
            float sr, sa;
            edge_geom(q.x - pp.x, q.y - pp.y, sr, sa);
            float4 WA, WR;
            decode_w(sr, sa, WA, WR);
            float2 fv = __ldg(&f2[nb * 4 + t]);
            accum16(WA, WR, pack2(fv.x, fv.y), Zp);
        }
    }

    // ---- Epilogue: pr[i] = sum_nm <K[i][jpair(t)][nm], Zp[nm]>, hadd ----
    float pr[8];
    #pragma unroll
    for (int i = 0; i < 8; ++i) {
        u64 acc = 0ull;
        #pragma unroll
        for (int nm2 = 0; nm2 < 8; ++nm2) {
            ulonglong2 kk = sk2[(i * 8 + nm2) * 4 + t];
            acc = fma2(kk.x, Zp[2 * nm2],     acc);
            acc = fma2(kk.y, Zp[2 * nm2 + 1], acc);
        }
        float lo, hi;
        unpack2(acc, lo, hi);
        pr[i] = lo + hi;
    }

    #pragma unroll
    for (int i = 0; i < 8; ++i) {
        pr[i] += __shfl_xor_sync(0xffffffffu, pr[i], 1);
        pr[i] += __shfl_xor_sync(0xffffffffu, pr[i], 2);
    }

    if (valid) {
        float o0 = pr[0], o1 = pr[4];
        if (t == 1) { o0 = pr[1]; o1 = pr[5]; }
        if (t == 2) { o0 = pr[2]; o1 = pr[6]; }
        if (t == 3) { o0 = pr[3]; o1 = pr[7]; }
        out[point * 8 + t]     = o0;
        out[point * 8 + 4 + t] = o1;
    }
}

extern "C" void kernel_launch(void* const* d_in, const int* in_sizes, int n_in,
                              void* d_out, int out_size)
{
    const float* positions  = (const float*)d_in[0];
    const float* features   = (const float*)d_in[1];
    const float* kernel     = (const float*)d_in[2];
    const int*   neighbors  = (const int*)d_in[3];
    const int*   row_splits = (const int*)d_in[4];
    float*       out        = (float*)d_out;

    int n_pts = in_sizes[0] / 2;
    int use_rec = (n_pts <= MAX_N) ? 1 : 0;

    if (use_rec) {
        pack_kernel<<<(n_pts + 255) / 256, 256>>>(
            (const float2*)positions, (const float2*)features, n_pts);
    }

    int blocks = (n_pts + PTS_PER_BLOCK - 1) / PTS_PER_BLOCK;
    rbf_layer_kernel<<<blocks, BLOCK_THREADS>>>(
        (const float2*)positions, features, kernel, neighbors, row_splits,
        out, n_pts, use_rec);
}